// round 17
// baseline (speedup 1.0000x reference)
#include <cuda_runtime.h>
#include <cuda_fp16.h>
#include <math.h>

#define NIMG 32768
#define KPAD 640
#define DIN  620

// ---- device scratch (allocation-free) ----
__device__ __align__(16) float g_feat[(size_t)NIMG * KPAD];
__device__ __align__(16) __half g_W1h16[20 * 1536 * 2];
__device__ __align__(16) __half g_W1l16[20 * 1536 * 2];
__device__ __align__(16) __half g_W2h16[3 * 1536 * 2];
__device__ __align__(16) __half g_W2l16[3 * 1536 * 2];
__device__ __align__(16) __half g_W3h16[3 * 1536 * 2];
__device__ __align__(16) __half g_W3l16[3 * 1536 * 2];

// ---- fp16 split helpers ----
__device__ __forceinline__ void split2(float x, float y, unsigned& hi, unsigned& lo) {
  __half hx = __float2half_rn(x);
  __half hy = __float2half_rn(y);
  __half lx = __float2half_rn(x - __half2float(hx));
  __half ly = __float2half_rn(y - __half2float(hy));
  __half2 ph = __halves2half2(hx, hy);
  __half2 pl = __halves2half2(lx, ly);
  hi = *(unsigned*)&ph;
  lo = *(unsigned*)&pl;
}

__device__ __forceinline__ void mma_f16(float* c, const unsigned* a,
                                        unsigned b0, unsigned b1) {
  asm volatile(
      "mma.sync.aligned.m16n8k16.row.col.f32.f16.f16.f32 "
      "{%0,%1,%2,%3}, {%4,%5,%6,%7}, {%8,%9}, {%0,%1,%2,%3};"
      : "+f"(c[0]), "+f"(c[1]), "+f"(c[2]), "+f"(c[3])
      : "r"(a[0]), "r"(a[1]), "r"(a[2]), "r"(a[3]), "r"(b0), "r"(b1));
}

__device__ __forceinline__ unsigned smem_u32(const void* p) {
  unsigned a;
  asm("{ .reg .u64 t; cvta.to.shared.u64 t, %1; cvt.u32.u64 %0, t; }" : "=r"(a) : "l"(p));
  return a;
}
__device__ __forceinline__ void cp16(unsigned dst, const void* src) {
  asm volatile("cp.async.ca.shared.global [%0], [%1], 16;" :: "r"(dst), "l"(src));
}
#define CP_COMMIT() asm volatile("cp.async.commit_group;" ::: "memory")
#define CP_WAIT0()  asm volatile("cp.async.wait_group 0;" ::: "memory")
#define CP_WAIT1()  asm volatile("cp.async.wait_group 1;" ::: "memory")

// ---------------------------------------------------------------------------
// Kernel A: top-200 stable selection + feature build, TWO images per block.
// tid = im*256 + t. Fast path scans bins >= 128 only; exact full fallback.
// Keys are monotone u64: (vbits<<32)|(~idx) -> stable rank = one u64 compare.
// ---------------------------------------------------------------------------
__global__ __launch_bounds__(512) void topk_feat_kernel(
    const float* __restrict__ images, const float* __restrict__ angles) {
  __shared__ unsigned int hist[512];
  __shared__ unsigned int above[512];
  __shared__ unsigned int cursor[512];
  __shared__ unsigned long long bucketed[1568];
  __shared__ unsigned int wtot[16];
  __shared__ unsigned int wsuf[16];
  __shared__ int sT[2];
  __shared__ unsigned int sTotal[2];

  const int tid = threadIdx.x;
  const int im = tid >> 8;
  const int t = tid & 255;
  const size_t img_id = (size_t)blockIdx.x * 2 + im;
  const float* img = images + img_id * 784;
  float* fo = g_feat + img_id * KPAD;

  if (t < 10) {
    float a = angles[img_id * 10 + t];
    float sn, cs;
    __sincosf(a, &sn, &cs);
    fo[600 + 2 * t] = cs;
    fo[601 + 2 * t] = sn;
  } else if (t < 30) {
    fo[620 + (t - 10)] = 0.f;  // pad k = 620..639
  }

  hist[tid] = 0u;
  cursor[tid] = 0u;
  __syncthreads();

  // Pass 1: 196 threads per image load float4; histogram bins >= 128 only
  float va[4];
  int qa[4];
  if (t < 196) {
    float4 v4 = *(const float4*)(img + t * 4);
    va[0] = v4.x; va[1] = v4.y; va[2] = v4.z; va[3] = v4.w;
#pragma unroll
    for (int j = 0; j < 4; j++) {
      qa[j] = (int)(va[j] * 256.0f);
      if (qa[j] >= 128) atomicAdd(&hist[im * 256 + qa[j]], 1u);
    }
  }
  __syncthreads();

  // Pass 2 (fast): suffix scan over bins 128..255 per image (warp-aligned)
  unsigned h = 0, s = 0;
  if (t < 128) {
    h = hist[im * 256 + 128 + t];
    s = h;
#pragma unroll
    for (int d = 1; d < 32; d <<= 1) {
      unsigned o = __shfl_down_sync(0xffffffffu, s, d);
      if ((t & 31) + d < 32) s += o;
    }
    if ((t & 31) == 0) wtot[im * 4 + (t >> 5)] = s;
  }
  __syncthreads();
  if (t < 4) {
    unsigned x = 0;
    for (int j = t + 1; j < 4; j++) x += wtot[im * 4 + j];
    wsuf[im * 4 + t] = x;
  }
  __syncthreads();
  if (t < 128) {
    unsigned a = (s - h) + wsuf[im * 4 + (t >> 5)];
    above[im * 256 + 128 + t] = a;
    if (a < 200u && a + h >= 200u) sT[im] = 128 + t;
    if (t == 0) sTotal[im] = a + h;  // count(q >= 128)
  }
  __syncthreads();

  // Exact fallback for BOTH images (essentially never taken for uniform inputs)
  if (sTotal[0] < 200u || sTotal[1] < 200u) {
    if (t < 196) {
#pragma unroll
      for (int j = 0; j < 4; j++) {
        if (qa[j] < 128) atomicAdd(&hist[im * 256 + qa[j]], 1u);
      }
    }
    __syncthreads();
    unsigned hf = hist[tid];
    unsigned sf = hf;
#pragma unroll
    for (int d = 1; d < 32; d <<= 1) {
      unsigned o = __shfl_down_sync(0xffffffffu, sf, d);
      if ((tid & 31) + d < 32) sf += o;
    }
    if ((tid & 31) == 0) wtot[tid >> 5] = sf;
    __syncthreads();
    if (t < 8) {
      unsigned x = 0;
      for (int j = t + 1; j < 8; j++) x += wtot[im * 8 + j];
      wsuf[im * 8 + t] = x;
    }
    __syncthreads();
    {
      unsigned a = (sf - hf) + wsuf[im * 8 + (t >> 5)];
      above[tid] = a;
      if (a < 200u && a + hf >= 200u) sT[im] = t;
    }
    __syncthreads();
  }
  const int T = sT[im];

  // Pass 3: scatter candidate keys (q >= T) into bucket-grouped slots
  if (t < 196) {
#pragma unroll
    for (int j = 0; j < 4; j++) {
      if (qa[j] >= T) {
        unsigned int pos = above[im * 256 + qa[j]] +
                           atomicAdd(&cursor[im * 256 + qa[j]], 1u);
        bucketed[im * 784 + pos] =
            ((unsigned long long)__float_as_uint(va[j]) << 32) |
            (unsigned int)(0xFFFFFFFFu - (unsigned)(t * 4 + j));
      }
    }
  }
  __syncthreads();

  // Pass 4: exact stable rank via single u64 compare per bucket-mate
  const int ncand = (int)(above[im * 256 + T] + hist[im * 256 + T]);
  for (int sI = t; sI < ncand; sI += 256) {
    unsigned long long key = bucketed[im * 784 + sI];
    unsigned int vb = (unsigned int)(key >> 32);
    unsigned int idx = 0xFFFFFFFFu - (unsigned int)(key & 0xFFFFFFFFu);
    float v = __uint_as_float(vb);
    int q = (int)(v * 256.0f);
    int lo = (int)above[im * 256 + q];
    int hi = lo + (int)hist[im * 256 + q];
    int rank = lo;
    for (int m = lo; m < hi; m++) {
      if (bucketed[im * 784 + m] > key) rank++;
    }
    if (rank < 200) {
      int r = (int)idx / 28;
      int c = (int)idx - r * 28;
      float cx = (c < 14) ? (float)(c - 14) : (float)(c - 13);
      float cy = (r < 14) ? (float)(14 - r) : (float)(13 - r);
      float vv = v;
      if (vv < 0.1f) { vv = 0.f; cx = 0.f; cy = 0.f; }
      fo[rank] = vv;
      *(float2*)(fo + 200 + 2 * rank) = make_float2(cx, cy);
    }
  }
}

// ---------------------------------------------------------------------------
// Weight prep: fp16 hi/lo split (x512), fragment-major for m16n8k16
// ---------------------------------------------------------------------------
__global__ void prep_weights(const float* __restrict__ W1,
                             const float* __restrict__ W2,
                             const float* __restrict__ W3) {
  int k = blockIdx.x;   // 0..639
  int n = threadIdx.x;  // 0..95
  int ch = k >> 5;
  int kk = k & 31;
  int kg = kk >> 4;
  int kk16 = kk & 15;
  int breg = kk16 >> 3;
  int tg = (kk16 & 7) >> 1;
  int pos = kk16 & 1;
  int g = n & 7;
  int nblk = n >> 3;
  size_t idx = ((size_t)ch * 1536 + (size_t)(kg * 12 + nblk) * 64 +
                (g * 4 + tg) * 2 + breg) * 2 + pos;
  {
    float v = ((k < DIN) ? W1[(size_t)k * 96 + n] : 0.f) * 512.0f;
    __half hh = __float2half_rn(v);
    __half hl = __float2half_rn(v - __half2float(hh));
    g_W1h16[idx] = hh;
    g_W1l16[idx] = hl;
  }
  if (k < 96) {
    float v2 = W2[(size_t)k * 96 + n] * 512.0f;
    __half h2 = __float2half_rn(v2);
    g_W2h16[idx] = h2;
    g_W2l16[idx] = __float2half_rn(v2 - __half2float(h2));
    float v3 = W3[(size_t)k * 96 + n] * 512.0f;
    __half h3 = __float2half_rn(v3);
    g_W3h16[idx] = h3;
    g_W3l16[idx] = __float2half_rn(v3 - __half2float(h3));
  }
}

// ---------------------------------------------------------------------------
// Kernel B: 3-term split-fp16 mma.sync MLP (m16n8k16), ping-pong W buffers
// ---------------------------------------------------------------------------
#define SBH0 0
#define SBL0 1536
#define SBH1 3072
#define SBL1 4608
#define SAH  6144
#define SAL  7200
#define SH   8256
#define SM_FLOATS 14656  // 58624 bytes

__device__ __forceinline__ void issue_W(unsigned smb, int sbh, int sbl,
                                        const __half* __restrict__ Wh,
                                        const __half* __restrict__ Wl,
                                        int ch, int tid) {
#pragma unroll
  for (int i = 0; i < 2; i++) {
    int idx = tid + i * 256;
    if (idx < 384) {
      cp16(smb + (sbh + idx * 4) * 4, Wh + (size_t)ch * 3072 + idx * 8);
      cp16(smb + (sbl + idx * 4) * 4, Wl + (size_t)ch * 3072 + idx * 8);
    }
  }
}

__global__ __launch_bounds__(256) void mlp_mma_kernel(
    const float* __restrict__ b1, const float* __restrict__ b2,
    const float* __restrict__ b3, const float* __restrict__ W4,
    const float* __restrict__ b4, float* __restrict__ outp) {
  extern __shared__ float sm[];
  const unsigned smb = smem_u32(sm);
  const int tid = threadIdx.x;
  const int warp = tid >> 5;
  const int lane = tid & 31;
  const int g = lane >> 2;
  const int tg = lane & 3;
  const int nbase = (warp & 3) * 24;
  const int mbase = (warp >> 2) * 32;
  const int row0 = blockIdx.x * 64;
  const float INV = 1.0f / 131072.0f;

  const int ar0 = tid >> 3, aq0 = tid & 7;
  const int ar1 = (tid + 256) >> 3, aq1 = (tid + 256) & 7;
  const int seg0 = ((aq0 >> 2) * 4 + (ar0 >> 4)) * 132 +
                   ((ar0 & 7) * 4 + 2 * (aq0 & 1)) * 4 +
                   ((aq0 >> 1) & 1) * 2 + ((ar0 >> 3) & 1);
  const int seg1 = ((aq1 >> 2) * 4 + (ar1 >> 4)) * 132 +
                   ((ar1 & 7) * 4 + 2 * (aq1 & 1)) * 4 +
                   ((aq1 >> 1) & 1) * 2 + ((ar1 >> 3) & 1);

  float c[3][2][4];
#pragma unroll
  for (int nt = 0; nt < 3; nt++)
#pragma unroll
    for (int mt = 0; mt < 2; mt++)
#pragma unroll
      for (int f = 0; f < 4; f++) c[nt][mt][f] = 0.f;

  float4 pfA0 = *(const float4*)(g_feat + (size_t)(row0 + ar0) * KPAD + aq0 * 4);
  float4 pfA1 = *(const float4*)(g_feat + (size_t)(row0 + ar1) * KPAD + aq1 * 4);
  issue_W(smb, SBH0, SBL0, g_W1h16, g_W1l16, 0, tid);
  CP_COMMIT();

  // ================= layer 1: K = 640, 20 chunks of 32 =================
  for (int ch = 0; ch < 20; ch++) {
    const int sbh = (ch & 1) ? SBH1 : SBH0;
    const int sbl = (ch & 1) ? SBL1 : SBL0;
    const int nsbh = (ch & 1) ? SBH0 : SBH1;
    const int nsbl = (ch & 1) ? SBL0 : SBL1;
    __syncthreads();
    if (ch + 1 < 20) {
      issue_W(smb, nsbh, nsbl, g_W1h16, g_W1l16, ch + 1, tid);
      CP_COMMIT();
    }
    {
      unsigned h01, l01, h23, l23;
      split2(pfA0.x * 256.f, pfA0.y * 256.f, h01, l01);
      split2(pfA0.z * 256.f, pfA0.w * 256.f, h23, l23);
      *(unsigned*)&sm[SAH + seg0] = h01;
      *(unsigned*)&sm[SAH + seg0 + 4] = h23;
      *(unsigned*)&sm[SAL + seg0] = l01;
      *(unsigned*)&sm[SAL + seg0 + 4] = l23;
      split2(pfA1.x * 256.f, pfA1.y * 256.f, h01, l01);
      split2(pfA1.z * 256.f, pfA1.w * 256.f, h23, l23);
      *(unsigned*)&sm[SAH + seg1] = h01;
      *(unsigned*)&sm[SAH + seg1 + 4] = h23;
      *(unsigned*)&sm[SAL + seg1] = l01;
      *(unsigned*)&sm[SAL + seg1 + 4] = l23;
    }
    if (ch + 1 < 20) {
      pfA0 = *(const float4*)(g_feat + (size_t)(row0 + ar0) * KPAD + (ch + 1) * 32 + aq0 * 4);
      pfA1 = *(const float4*)(g_feat + (size_t)(row0 + ar1) * KPAD + (ch + 1) * 32 + aq1 * 4);
      CP_WAIT1();
    } else {
      CP_WAIT0();
    }
    __syncthreads();

#pragma unroll
    for (int kg = 0; kg < 2; kg++) {
      float4 ahf[2], alf[2];
#pragma unroll
      for (int mt = 0; mt < 2; mt++) {
        int mb = (warp >> 2) * 2 + mt;
        int off = (kg * 4 + mb) * 132 + lane * 4;
        ahf[mt] = *(const float4*)(sm + SAH + off);
        alf[mt] = *(const float4*)(sm + SAL + off);
      }
#pragma unroll
      for (int nt = 0; nt < 3; nt++) {
        int nblk = (warp & 3) * 3 + nt;
        int boff = (kg * 12 + nblk) * 64 + lane * 2;
        float2 bh = *(const float2*)(sm + sbh + boff);
        float2 bl = *(const float2*)(sm + sbl + boff);
        unsigned b0h = __float_as_uint(bh.x), b1h = __float_as_uint(bh.y);
        unsigned b0l = __float_as_uint(bl.x), b1l = __float_as_uint(bl.y);
#pragma unroll
        for (int mt = 0; mt < 2; mt++) {
          mma_f16(c[nt][mt], (const unsigned*)&ahf[mt], b0h, b1h);
          mma_f16(c[nt][mt], (const unsigned*)&ahf[mt], b0l, b1l);
          mma_f16(c[nt][mt], (const unsigned*)&alf[mt], b0h, b1h);
        }
      }
    }
  }

  // layer-1 writeback: unscale + bias + relu -> sH
  __syncthreads();
#pragma unroll
  for (int nt = 0; nt < 3; nt++) {
#pragma unroll
    for (int mt = 0; mt < 2; mt++) {
      int col = nbase + nt * 8 + 2 * tg;
      int r0 = mbase + mt * 16 + g;
      float bb0 = __ldg(b1 + col), bb1 = __ldg(b1 + col + 1);
      sm[SH + r0 * 100 + col] = fmaxf(fmaf(c[nt][mt][0], INV, bb0), 0.f);
      sm[SH + r0 * 100 + col + 1] = fmaxf(fmaf(c[nt][mt][1], INV, bb1), 0.f);
      sm[SH + (r0 + 8) * 100 + col] = fmaxf(fmaf(c[nt][mt][2], INV, bb0), 0.f);
      sm[SH + (r0 + 8) * 100 + col + 1] = fmaxf(fmaf(c[nt][mt][3], INV, bb1), 0.f);
#pragma unroll
      for (int f = 0; f < 4; f++) c[nt][mt][f] = 0.f;
    }
  }
  __syncthreads();

  // ================= layers 2 & 3: K = 96, 3 chunks of 32 =================
#pragma unroll 1
  for (int L = 0; L < 2; L++) {
    const __half* Wh = L ? g_W3h16 : g_W2h16;
    const __half* Wl = L ? g_W3l16 : g_W2l16;
    const float* bias = L ? b3 : b2;

    issue_W(smb, SBH0, SBL0, Wh, Wl, 0, tid);
    CP_COMMIT();

#pragma unroll 1
    for (int ch = 0; ch < 3; ch++) {
      const int sbh = (ch & 1) ? SBH1 : SBH0;
      const int sbl = (ch & 1) ? SBL1 : SBL0;
      const int nsbh = (ch & 1) ? SBH0 : SBH1;
      const int nsbl = (ch & 1) ? SBL0 : SBL1;
      __syncthreads();
      if (ch + 1 < 3) {
        issue_W(smb, nsbh, nsbl, Wh, Wl, ch + 1, tid);
        CP_COMMIT();
        CP_WAIT1();
      } else {
        CP_WAIT0();
      }
      __syncthreads();

#pragma unroll
      for (int kg = 0; kg < 2; kg++) {
        int ka = ch * 32 + kg * 16;
        unsigned ah[2][4], al[2][4];
#pragma unroll
        for (int mt = 0; mt < 2; mt++) {
          int r = mbase + mt * 16 + g;
          const float* p0 = sm + SH + r * 100 + ka;
          const float* p1 = sm + SH + (r + 8) * 100 + ka;
          int c0 = 2 * tg, c1 = 2 * tg + 8;
          split2(p0[c0] * 256.f, p0[c0 + 1] * 256.f, ah[mt][0], al[mt][0]);
          split2(p1[c0] * 256.f, p1[c0 + 1] * 256.f, ah[mt][1], al[mt][1]);
          split2(p0[c1] * 256.f, p0[c1 + 1] * 256.f, ah[mt][2], al[mt][2]);
          split2(p1[c1] * 256.f, p1[c1 + 1] * 256.f, ah[mt][3], al[mt][3]);
        }
#pragma unroll
        for (int nt = 0; nt < 3; nt++) {
          int nblk = (warp & 3) * 3 + nt;
          int boff = (kg * 12 + nblk) * 64 + lane * 2;
          float2 bh = *(const float2*)(sm + sbh + boff);
          float2 bl = *(const float2*)(sm + sbl + boff);
          unsigned b0h = __float_as_uint(bh.x), b1h = __float_as_uint(bh.y);
          unsigned b0l = __float_as_uint(bl.x), b1l = __float_as_uint(bl.y);
#pragma unroll
          for (int mt = 0; mt < 2; mt++) {
            mma_f16(c[nt][mt], ah[mt], b0h, b1h);
            mma_f16(c[nt][mt], ah[mt], b0l, b1l);
            mma_f16(c[nt][mt], al[mt], b0h, b1h);
          }
        }
      }
    }

    __syncthreads();
#pragma unroll
    for (int nt = 0; nt < 3; nt++) {
#pragma unroll
      for (int mt = 0; mt < 2; mt++) {
        int col = nbase + nt * 8 + 2 * tg;
        int r0 = mbase + mt * 16 + g;
        float bb0 = __ldg(bias + col), bb1 = __ldg(bias + col + 1);
        sm[SH + r0 * 100 + col] = fmaxf(fmaf(c[nt][mt][0], INV, bb0), 0.f);
        sm[SH + r0 * 100 + col + 1] = fmaxf(fmaf(c[nt][mt][1], INV, bb1), 0.f);
        sm[SH + (r0 + 8) * 100 + col] = fmaxf(fmaf(c[nt][mt][2], INV, bb0), 0.f);
        sm[SH + (r0 + 8) * 100 + col + 1] = fmaxf(fmaf(c[nt][mt][3], INV, bb1), 0.f);
#pragma unroll
        for (int f = 0; f < 4; f++) c[nt][mt][f] = 0.f;
      }
    }
    __syncthreads();
  }

  // ================= layer 4 (96 -> 4) + Gram-Schmidt =================
  if (tid < 64) {
    float o0 = 0.f, o1 = 0.f, o2 = 0.f, o3 = 0.f;
#pragma unroll 4
    for (int k = 0; k < 96; k++) {
      float hv = sm[SH + tid * 100 + k];
      float4 w = *(const float4*)(W4 + (size_t)k * 4);
      o0 = fmaf(hv, w.x, o0);
      o1 = fmaf(hv, w.y, o1);
      o2 = fmaf(hv, w.z, o2);
      o3 = fmaf(hv, w.w, o3);
    }
    float4 bv = *(const float4*)(b4);
    o0 += bv.x; o1 += bv.y; o2 += bv.z; o3 += bv.w;

    float n0 = 1.0f / sqrtf(o0 * o0 + o1 * o1);
    float e0x = o0 * n0, e0y = o1 * n0;
    float dt = e0x * o2 + e0y * o3;
    float u1x = o2 - dt * e0x, u1y = o3 - dt * e0y;
    float n1 = 1.0f / sqrtf(u1x * u1x + u1y * u1y);
    float e1x = u1x * n1, e1y = u1y * n1;
    float det = e0x * e1y - e1x * e0y;

    float* po = outp + (size_t)(row0 + tid) * 4;
    po[0] = e0x * det;
    po[1] = e1x;
    po[2] = e0y * det;
    po[3] = e1y;
  }
}

// ---------------------------------------------------------------------------
extern "C" void kernel_launch(void* const* d_in, const int* in_sizes, int n_in,
                              void* d_out, int out_size) {
  (void)in_sizes; (void)n_in; (void)out_size;
  const float* images = (const float*)d_in[0];
  const float* angles = (const float*)d_in[1];
  const float* W1 = (const float*)d_in[2];
  const float* b1 = (const float*)d_in[3];
  const float* W2 = (const float*)d_in[4];
  const float* b2 = (const float*)d_in[5];
  const float* W3 = (const float*)d_in[6];
  const float* b3 = (const float*)d_in[7];
  const float* W4 = (const float*)d_in[8];
  const float* b4 = (const float*)d_in[9];
  float* outp = (float*)d_out;

  cudaFuncSetAttribute(mlp_mma_kernel, cudaFuncAttributeMaxDynamicSharedMemorySize,
                       SM_FLOATS * 4);

  topk_feat_kernel<<<NIMG / 2, 512>>>(images, angles);
  prep_weights<<<KPAD, 96>>>(W1, W2, W3);
  mlp_mma_kernel<<<NIMG / 64, 256, SM_FLOATS * 4>>>(b1, b2, b3, W4, b4, outp);
}